// round 6
// baseline (speedup 1.0000x reference)
#include <cuda_runtime.h>

// Problem dims (fixed)
#define BB   512
#define TT   100
#define II   700
#define HH   128
#define OO   20
#define NROWS (BB*TT)
#define MW   24                    // padded mask words per row (22 used + 2 zero)

#define ALPHA 0.81873075307798182f // exp(-0.2)
#define BETA  0.90483741803595957f // exp(-0.1)
#define LAM   0.95122942450071400f // exp(-0.05)

// Device-global scratch (allocation-free)
static __device__ float    g_W0T[II * HH];               // W0^T [i][h]
static __device__ unsigned g_masks[(size_t)NROWS * MW];  // input spike bitmasks (SEQUENTIAL)
static __device__ float    g_U[(size_t)NROWS * HH];      // U = X @ W0^T
static __device__ unsigned g_K0[(size_t)NROWS * 4];      // layer-0 spike masks
static __device__ float    g_G[(size_t)NROWS * HH];      // G = k0 @ W1^T

// ---------------------------------------------------------------------------
// K1: transpose W0 (H,I) -> W0^T (I,H)
// ---------------------------------------------------------------------------
__global__ void k_transpose_w0(const float* __restrict__ W0) {
    int idx = blockIdx.x * blockDim.x + threadIdx.x;
    if (idx < II * HH) {
        int i = idx >> 7, h = idx & 127;
        g_W0T[idx] = W0[h * II + i];
    }
}

// ---------------------------------------------------------------------------
// K2: input spike bitmasks, float4 loads, SEQUENTIAL bit order.
// Lane loads elements 4*(32k+lane)..+3 as one float4 -> 4-bit nibble.
// 8-lane shfl_xor OR-reduce assembles word w: bit j == element 32w+j,
// exactly matching the R3 scalar encoding (accumulation order preserved).
// ---------------------------------------------------------------------------
__global__ void __launch_bounds__(256) k_masks(const float* __restrict__ X) {
    int warp = (blockIdx.x * 256 + threadIdx.x) >> 5;
    int lane = threadIdx.x & 31;
    if (warp >= NROWS) return;
    const float4* xr4 = (const float4*)(X + (size_t)warp * II);

    unsigned mw = 0;                      // word `lane` of this row
    int myk = lane >> 2;                  // chunk that produces my word
    int myg = lane & 3;                   // word-group within that chunk
    #pragma unroll
    for (int k = 0; k < 6; k++) {
        float4 v = make_float4(0.f, 0.f, 0.f, 0.f);
        if (k < 5 || lane < 15)           // chunk 5: elements 640..699 only
            v = __ldg(xr4 + k * 32 + lane);
        unsigned nib = (v.x != 0.f ? 1u : 0u) | (v.y != 0.f ? 2u : 0u)
                     | (v.z != 0.f ? 4u : 0u) | (v.w != 0.f ? 8u : 0u);
        unsigned part = nib << ((lane & 7) * 4);
        part |= __shfl_xor_sync(0xffffffffu, part, 1);
        part |= __shfl_xor_sync(0xffffffffu, part, 2);
        part |= __shfl_xor_sync(0xffffffffu, part, 4);
        // group g (lanes 8g..8g+7) now all hold word 4k+g
        unsigned wd = __shfl_sync(0xffffffffu, part, myg * 8);
        if (k == myk) mw = wd;
    }
    if (lane < MW) g_masks[(size_t)warp * MW + lane] = mw;
}

// ---------------------------------------------------------------------------
// K3: U[row, quarter] = sum over active i (ascending) of W0T[i, quarter].
// 89.6 KB SMEM quarter per CTA, 2 CTAs/SM, 32 warps/SM. Warp per row.
// ---------------------------------------------------------------------------
__global__ void __launch_bounds__(512, 2) k_gather() {
    extern __shared__ float Ws[];              // [700][32]
    const int quarter = blockIdx.y;

    for (int idx = threadIdx.x; idx < II * 32; idx += 512) {
        int i = idx >> 5, q = idx & 31;
        Ws[idx] = g_W0T[i * HH + quarter * 32 + q];
    }
    __syncthreads();

    int warp = threadIdx.x >> 5, lane = threadIdx.x & 31;
    const int rows_per_cta = (NROWS + gridDim.x - 1) / gridDim.x;
    int r0 = blockIdx.x * rows_per_cta;
    int r1 = min(r0 + rows_per_cta, NROWS);

    for (int row = r0 + warp; row < r1; row += 16) {
        unsigned mw = (lane < MW) ? g_masks[(size_t)row * MW + lane] : 0u;
        float acc = 0.f;
        #pragma unroll
        for (int w = 0; w < MW; w++) {
            unsigned m = __shfl_sync(0xffffffffu, mw, w);
            int base = w * 32;                  // element = base + j (ascending)
            while (m) {
                int j = __ffs(m) - 1;
                m &= m - 1;
                acc += Ws[(base + j) * 32 + lane];
            }
        }
        g_U[(size_t)row * HH + quarter * 32 + lane] = acc;
    }
}

// ---------------------------------------------------------------------------
// K4: layer-0 LIF scan, prefetch depth 4. Warp = (sample, 32-neuron chunk).
// ---------------------------------------------------------------------------
__global__ void __launch_bounds__(256) k_layer0() {
    int w = blockIdx.x * 8 + (threadIdx.x >> 5);
    int lane = threadIdx.x & 31;
    int b = w >> 2, c = w & 3;
    if (b >= BB) return;

    const float* Ub = g_U + (size_t)b * TT * HH + c * 32 + lane;
    unsigned* K0b = g_K0 + (size_t)b * TT * 4 + c;

    float s0 = 0.f, m0 = 0.f;
    float buf[4];
    #pragma unroll
    for (int r = 0; r < 4; r++) buf[r] = Ub[(size_t)r * HH];

    for (int t0 = 0; t0 < TT; t0 += 4) {
        float nxt[4];
        #pragma unroll
        for (int r = 0; r < 4; r++) {
            int tn = t0 + 4 + r;
            nxt[r] = (tn < TT) ? Ub[(size_t)tn * HH] : 0.f;
        }
        #pragma unroll
        for (int r = 0; r < 4; r++) {
            s0 = ALPHA * s0 + buf[r];
            m0 = BETA * m0 + s0;
            bool sp = m0 > 1.0f;
            if (sp) m0 = 0.f;
            unsigned bm = __ballot_sync(0xffffffffu, sp);
            if (lane == 0) K0b[(size_t)(t0 + r) * 4] = bm;
        }
        #pragma unroll
        for (int r = 0; r < 4; r++) buf[r] = nxt[r];
    }
}

// ---------------------------------------------------------------------------
// K5: G[row] = sum over active j (k0, ascending) of W1T[j]. 64 KB SMEM.
// ---------------------------------------------------------------------------
__global__ void __launch_bounds__(512) k_gatherG(const float* __restrict__ W1) {
    extern __shared__ float W1s[];             // [128][128]
    for (int idx = threadIdx.x; idx < HH * HH; idx += 512) {
        int h = idx >> 7, j = idx & 127;
        W1s[j * 128 + h] = W1[idx];
    }
    __syncthreads();

    int warp = threadIdx.x >> 5, lane = threadIdx.x & 31;
    int gw = blockIdx.x * 16 + warp;
    int stride = gridDim.x * 16;

    for (int row = gw; row < NROWS; row += stride) {
        unsigned mw = (lane < 4) ? g_K0[(size_t)row * 4 + lane] : 0u;
        float4 acc = make_float4(0.f, 0.f, 0.f, 0.f);
        #pragma unroll
        for (int q = 0; q < 4; q++) {
            unsigned m = __shfl_sync(0xffffffffu, mw, q);
            int base = q * 32;
            while (m) {
                int j = __ffs(m) - 1;
                m &= m - 1;
                float4 v = *(const float4*)(W1s + (base + j) * 128 + lane * 4);
                acc.x += v.x; acc.y += v.y; acc.z += v.z; acc.w += v.w;
            }
        }
        *(float4*)(g_G + (size_t)row * HH + lane * 4) = acc;
    }
}

// ---------------------------------------------------------------------------
// K6: FUSED layer-1 recurrence + readout gather + leaky scan.
// 2 samples/CTA (256 thr), 2 CTAs/SM. V1^T (stride 129) + Wr^T + br in SMEM.
// ---------------------------------------------------------------------------
__global__ void __launch_bounds__(256, 2) k_layer1(
    const float* __restrict__ V1, const float* __restrict__ Wr,
    const float* __restrict__ br, float* __restrict__ out)
{
    extern __shared__ float sm6[];
    float* V1s = sm6;                               // 128*129
    float* Wrs = V1s + HH * 129;                    // 128*20
    float* brs = Wrs + HH * OO;                     // 32 (padded)
    unsigned* km = (unsigned*)(brs + 32);           // [2 samples][2 bufs][4]

    for (int idx = threadIdx.x; idx < HH * HH; idx += 256) {
        int h = idx >> 7, j = idx & 127;
        V1s[j * 129 + h] = V1[idx];
    }
    for (int idx = threadIdx.x; idx < OO * HH; idx += 256) {
        int o = idx >> 7, j = idx & 127;
        Wrs[j * OO + o] = Wr[idx];
    }
    if (threadIdx.x < OO) brs[threadIdx.x] = br[threadIdx.x];
    __syncthreads();

    int g    = threadIdx.x >> 7;     // sample in CTA
    int h    = threadIdx.x & 127;    // neuron
    int word = h >> 5;
    int lane = threadIdx.x & 31;
    int b    = blockIdx.x * 2 + g;
    unsigned* kg = km + g * 8;
    int barid = g + 1;
    int ro = (lane < OO) ? lane : 0;

    const float* Gb = g_G + (size_t)b * TT * HH;
    float* outb = out + (size_t)b * TT * OO;

    float s1 = 0.f, m1 = 0.f, rp = 0.f;
    float brv = brs[ro];
    unsigned p0 = 0, p1 = 0, p2 = 0, p3 = 0;
    float gv = Gb[h];

    for (int t = 0; t < TT; t++) {
        float gn = (t + 1 < TT) ? Gb[(size_t)(t + 1) * HH + h] : 0.f;

        float acc = 0.f;
        unsigned m;
        m = p0; while (m) { int j = __ffs(m) - 1; m &= m - 1; acc += V1s[j * 129 + h]; }
        m = p1; while (m) { int j = __ffs(m) - 1; m &= m - 1; acc += V1s[(32 + j) * 129 + h]; }
        m = p2; while (m) { int j = __ffs(m) - 1; m &= m - 1; acc += V1s[(64 + j) * 129 + h]; }
        m = p3; while (m) { int j = __ffs(m) - 1; m &= m - 1; acc += V1s[(96 + j) * 129 + h]; }

        s1 = (ALPHA * s1 + gv) + acc;
        m1 = BETA * m1 + s1;
        bool sp = m1 > 1.0f;
        if (sp) m1 = 0.f;

        unsigned bm = __ballot_sync(0xffffffffu, sp);
        int buf = (t & 1) * 4;
        if (lane == 0) kg[buf + word] = bm;
        asm volatile("bar.sync %0, %1;" :: "r"(barid), "r"(128) : "memory");
        unsigned n0 = kg[buf + 0], n1 = kg[buf + 1];
        unsigned n2 = kg[buf + 2], n3 = kg[buf + 3];

        if (h < 32) {  // group's first warp: readout + leaky scan
            float racc = brv;
            m = n0; while (m) { int j = __ffs(m) - 1; m &= m - 1; racc += Wrs[j * OO + ro]; }
            m = n1; while (m) { int j = __ffs(m) - 1; m &= m - 1; racc += Wrs[(32 + j) * OO + ro]; }
            m = n2; while (m) { int j = __ffs(m) - 1; m &= m - 1; racc += Wrs[(64 + j) * OO + ro]; }
            m = n3; while (m) { int j = __ffs(m) - 1; m &= m - 1; racc += Wrs[(96 + j) * OO + ro]; }
            rp = LAM * rp + (1.0f - LAM) * racc;
            if (lane < OO) outb[(size_t)t * OO + lane] = rp;
        }
        p0 = n0; p1 = n1; p2 = n2; p3 = n3;
        gv = gn;
    }
}

// ---------------------------------------------------------------------------
// Launch
// ---------------------------------------------------------------------------
extern "C" void kernel_launch(void* const* d_in, const int* in_sizes, int n_in,
                              void* d_out, int out_size) {
    (void)in_sizes; (void)n_in; (void)out_size;
    const float* X  = (const float*)d_in[0];
    const float* W0 = (const float*)d_in[1];
    const float* W1 = (const float*)d_in[2];
    const float* V1 = (const float*)d_in[3];
    const float* Wr = (const float*)d_in[4];
    const float* br = (const float*)d_in[5];
    float* out = (float*)d_out;

    k_transpose_w0<<<(II * HH + 255) / 256, 256>>>(W0);
    k_masks<<<(NROWS + 7) / 8, 256>>>(X);

    const size_t smem_g = (size_t)II * 32 * sizeof(float);   // 89,600 B
    cudaFuncSetAttribute(k_gather, cudaFuncAttributeMaxDynamicSharedMemorySize,
                         (int)smem_g);
    k_gather<<<dim3(74, 4), 512, smem_g>>>();

    k_layer0<<<256, 256>>>();

    const size_t smem_g1 = (size_t)HH * HH * sizeof(float);  // 64 KB
    cudaFuncSetAttribute(k_gatherG, cudaFuncAttributeMaxDynamicSharedMemorySize,
                         (int)smem_g1);
    k_gatherG<<<296, 512, smem_g1>>>(W1);

    const size_t smem_l1 = (size_t)(HH * 129 + HH * OO + 32) * sizeof(float)
                         + 16 * sizeof(unsigned);            // ~76.5 KB
    cudaFuncSetAttribute(k_layer1, cudaFuncAttributeMaxDynamicSharedMemorySize,
                         (int)smem_l1);
    k_layer1<<<BB / 2, 256, smem_l1>>>(V1, Wr, br, out);
}

// round 7
// speedup vs baseline: 1.1924x; 1.1924x over previous
#include <cuda_runtime.h>

// Problem dims (fixed)
#define BB   512
#define TT   100
#define II   700
#define HH   128
#define OO   20
#define NROWS (BB*TT)
#define MW   24                    // padded mask words per row (22 used + 2 zero)
#define CHUNK_I 192                // i-rows per gather chunk (6 words)
#define CHUNK_W 6                  // mask words per chunk

#define ALPHA 0.81873075307798182f // exp(-0.2)
#define BETA  0.90483741803595957f // exp(-0.1)
#define LAM   0.95122942450071400f // exp(-0.05)

// Device-global scratch (allocation-free)
static __device__ float    g_W0T[II * HH];               // W0^T [i][h]
static __device__ unsigned g_masks[(size_t)NROWS * MW];  // input spike bitmasks (sequential order)
static __device__ float    g_U[(size_t)NROWS * HH];      // U = X @ W0^T (running acc across chunks)
static __device__ unsigned g_K0[(size_t)NROWS * 4];      // layer-0 spike masks
static __device__ float    g_G[(size_t)NROWS * HH];      // G = k0 @ W1^T

// ---------------------------------------------------------------------------
// K1: transpose W0 (H,I) -> W0^T (I,H)
// ---------------------------------------------------------------------------
__global__ void k_transpose_w0(const float* __restrict__ W0) {
    int idx = blockIdx.x * blockDim.x + threadIdx.x;
    if (idx < II * HH) {
        int i = idx >> 7, h = idx & 127;
        g_W0T[idx] = W0[h * II + i];
    }
}

// ---------------------------------------------------------------------------
// K2: input spike bitmasks, float4 loads, SEQUENTIAL bit order (bit-exact
// with the scalar encoding: word w bit j <-> element 32w+j).
// ---------------------------------------------------------------------------
__global__ void __launch_bounds__(256) k_masks(const float* __restrict__ X) {
    int warp = (blockIdx.x * 256 + threadIdx.x) >> 5;
    int lane = threadIdx.x & 31;
    if (warp >= NROWS) return;
    const float4* xr4 = (const float4*)(X + (size_t)warp * II);

    unsigned mw = 0;                      // word `lane` of this row
    int myk = lane >> 2;                  // chunk that produces my word
    int myg = lane & 3;                   // word-group within that chunk
    #pragma unroll
    for (int k = 0; k < 6; k++) {
        float4 v = make_float4(0.f, 0.f, 0.f, 0.f);
        if (k < 5 || lane < 15)           // chunk 5: elements 640..699 only
            v = __ldg(xr4 + k * 32 + lane);
        unsigned nib = (v.x != 0.f ? 1u : 0u) | (v.y != 0.f ? 2u : 0u)
                     | (v.z != 0.f ? 4u : 0u) | (v.w != 0.f ? 8u : 0u);
        unsigned part = nib << ((lane & 7) * 4);
        part |= __shfl_xor_sync(0xffffffffu, part, 1);
        part |= __shfl_xor_sync(0xffffffffu, part, 2);
        part |= __shfl_xor_sync(0xffffffffu, part, 4);
        unsigned wd = __shfl_sync(0xffffffffu, part, myg * 8);
        if (k == myk) mw = wd;
    }
    if (lane < MW) g_masks[(size_t)warp * MW + lane] = mw;
}

// ---------------------------------------------------------------------------
// K3: U chunk pass. Chunk c holds W0^T rows [192c, 192c+192) x all 128 h in
// 98 KB SMEM (2 CTAs/SM, 32 warps/SM). Warp per row, float4 per lane
// (full 128-h width -> minimal decode overhead). The accumulator is carried
// through g_U across the 4 sequential launches; element additions happen
// one-at-a-time in ascending i, so the float sequence is bit-identical to a
// single ascending sweep.
// ---------------------------------------------------------------------------
__global__ void __launch_bounds__(512, 2) k_gather(int chunk) {
    extern __shared__ float4 Ws4[];            // [192][32] float4
    const int w0 = chunk * CHUNK_W;            // first mask word of chunk

    for (int idx = threadIdx.x; idx < CHUNK_I * 32; idx += 512) {
        int i = idx >> 5, q = idx & 31;
        int gi = chunk * CHUNK_I + i;
        float4 v = make_float4(0.f, 0.f, 0.f, 0.f);
        if (gi < II) v = *(const float4*)(g_W0T + gi * HH + q * 4);
        Ws4[idx] = v;
    }
    __syncthreads();

    int warp = threadIdx.x >> 5, lane = threadIdx.x & 31;
    for (int row = blockIdx.x * 16 + warp; row < NROWS; row += gridDim.x * 16) {
        unsigned mw = (lane < CHUNK_W)
                    ? g_masks[(size_t)row * MW + w0 + lane] : 0u;
        float4* up = (float4*)(g_U + (size_t)row * HH) + lane;
        float4 acc;
        if (chunk == 0) acc = make_float4(0.f, 0.f, 0.f, 0.f);
        else            acc = *up;
        #pragma unroll
        for (int w = 0; w < CHUNK_W; w++) {
            unsigned m = __shfl_sync(0xffffffffu, mw, w);
            int base = w * 32;
            while (m) {
                int j = __ffs(m) - 1;
                m &= m - 1;
                float4 v = Ws4[(base + j) * 32 + lane];
                acc.x += v.x; acc.y += v.y; acc.z += v.z; acc.w += v.w;
            }
        }
        *up = acc;
    }
}

// ---------------------------------------------------------------------------
// K4: layer-0 LIF scan, prefetch depth 4. Warp = (sample, 32-neuron chunk).
// ---------------------------------------------------------------------------
__global__ void __launch_bounds__(256) k_layer0() {
    int w = blockIdx.x * 8 + (threadIdx.x >> 5);
    int lane = threadIdx.x & 31;
    int b = w >> 2, c = w & 3;
    if (b >= BB) return;

    const float* Ub = g_U + (size_t)b * TT * HH + c * 32 + lane;
    unsigned* K0b = g_K0 + (size_t)b * TT * 4 + c;

    float s0 = 0.f, m0 = 0.f;
    float buf[4];
    #pragma unroll
    for (int r = 0; r < 4; r++) buf[r] = Ub[(size_t)r * HH];

    for (int t0 = 0; t0 < TT; t0 += 4) {
        float nxt[4];
        #pragma unroll
        for (int r = 0; r < 4; r++) {
            int tn = t0 + 4 + r;
            nxt[r] = (tn < TT) ? Ub[(size_t)tn * HH] : 0.f;
        }
        #pragma unroll
        for (int r = 0; r < 4; r++) {
            s0 = ALPHA * s0 + buf[r];
            m0 = BETA * m0 + s0;
            bool sp = m0 > 1.0f;
            if (sp) m0 = 0.f;
            unsigned bm = __ballot_sync(0xffffffffu, sp);
            if (lane == 0) K0b[(size_t)(t0 + r) * 4] = bm;
        }
        #pragma unroll
        for (int r = 0; r < 4; r++) buf[r] = nxt[r];
    }
}

// ---------------------------------------------------------------------------
// K5: G[row] = sum over active j (k0, ascending) of W1T[j]. 64 KB SMEM,
// full-width float4, 2 CTAs/SM.
// ---------------------------------------------------------------------------
__global__ void __launch_bounds__(512, 2) k_gatherG(const float* __restrict__ W1) {
    extern __shared__ float W1s[];             // [128][128]
    for (int idx = threadIdx.x; idx < HH * HH; idx += 512) {
        int h = idx >> 7, j = idx & 127;
        W1s[j * 128 + h] = W1[idx];
    }
    __syncthreads();

    int warp = threadIdx.x >> 5, lane = threadIdx.x & 31;
    int gw = blockIdx.x * 16 + warp;
    int stride = gridDim.x * 16;

    for (int row = gw; row < NROWS; row += stride) {
        unsigned mw = (lane < 4) ? g_K0[(size_t)row * 4 + lane] : 0u;
        float4 acc = make_float4(0.f, 0.f, 0.f, 0.f);
        #pragma unroll
        for (int q = 0; q < 4; q++) {
            unsigned m = __shfl_sync(0xffffffffu, mw, q);
            int base = q * 32;
            while (m) {
                int j = __ffs(m) - 1;
                m &= m - 1;
                float4 v = *(const float4*)(W1s + (base + j) * 128 + lane * 4);
                acc.x += v.x; acc.y += v.y; acc.z += v.z; acc.w += v.w;
            }
        }
        *(float4*)(g_G + (size_t)row * HH + lane * 4) = acc;
    }
}

// ---------------------------------------------------------------------------
// K6: FUSED layer-1 recurrence + readout gather + leaky scan.
// 2 samples/CTA (256 thr), 2 CTAs/SM. V1^T (stride 128, h-contiguous ->
// conflict-free) + Wr^T + br in SMEM.
// ---------------------------------------------------------------------------
__global__ void __launch_bounds__(256, 2) k_layer1(
    const float* __restrict__ V1, const float* __restrict__ Wr,
    const float* __restrict__ br, float* __restrict__ out)
{
    extern __shared__ float sm6[];
    float* V1s = sm6;                               // 128*128
    float* Wrs = V1s + HH * HH;                     // 128*20
    float* brs = Wrs + HH * OO;                     // 32 (padded)
    unsigned* km = (unsigned*)(brs + 32);           // [2 samples][2 bufs][4]

    for (int idx = threadIdx.x; idx < HH * HH; idx += 256) {
        int h = idx >> 7, j = idx & 127;
        V1s[j * 128 + h] = V1[idx];
    }
    for (int idx = threadIdx.x; idx < OO * HH; idx += 256) {
        int o = idx >> 7, j = idx & 127;
        Wrs[j * OO + o] = Wr[idx];
    }
    if (threadIdx.x < OO) brs[threadIdx.x] = br[threadIdx.x];
    __syncthreads();

    int g    = threadIdx.x >> 7;     // sample in CTA
    int h    = threadIdx.x & 127;    // neuron
    int word = h >> 5;
    int lane = threadIdx.x & 31;
    int b    = blockIdx.x * 2 + g;
    unsigned* kg = km + g * 8;
    int barid = g + 1;
    int ro = (lane < OO) ? lane : 0;

    const float* Gb = g_G + (size_t)b * TT * HH;
    float* outb = out + (size_t)b * TT * OO;

    float s1 = 0.f, m1 = 0.f, rp = 0.f;
    float brv = brs[ro];
    unsigned p0 = 0, p1 = 0, p2 = 0, p3 = 0;
    float gv = Gb[h];

    for (int t = 0; t < TT; t++) {
        float gn = (t + 1 < TT) ? Gb[(size_t)(t + 1) * HH + h] : 0.f;

        float acc = 0.f;
        unsigned m;
        m = p0; while (m) { int j = __ffs(m) - 1; m &= m - 1; acc += V1s[j * 128 + h]; }
        m = p1; while (m) { int j = __ffs(m) - 1; m &= m - 1; acc += V1s[(32 + j) * 128 + h]; }
        m = p2; while (m) { int j = __ffs(m) - 1; m &= m - 1; acc += V1s[(64 + j) * 128 + h]; }
        m = p3; while (m) { int j = __ffs(m) - 1; m &= m - 1; acc += V1s[(96 + j) * 128 + h]; }

        s1 = (ALPHA * s1 + gv) + acc;
        m1 = BETA * m1 + s1;
        bool sp = m1 > 1.0f;
        if (sp) m1 = 0.f;

        unsigned bm = __ballot_sync(0xffffffffu, sp);
        int buf = (t & 1) * 4;
        if (lane == 0) kg[buf + word] = bm;
        asm volatile("bar.sync %0, %1;" :: "r"(barid), "r"(128) : "memory");
        unsigned n0 = kg[buf + 0], n1 = kg[buf + 1];
        unsigned n2 = kg[buf + 2], n3 = kg[buf + 3];

        if (h < 32) {  // group's first warp: readout + leaky scan
            float racc = brv;
            m = n0; while (m) { int j = __ffs(m) - 1; m &= m - 1; racc += Wrs[j * OO + ro]; }
            m = n1; while (m) { int j = __ffs(m) - 1; m &= m - 1; racc += Wrs[(32 + j) * OO + ro]; }
            m = n2; while (m) { int j = __ffs(m) - 1; m &= m - 1; racc += Wrs[(64 + j) * OO + ro]; }
            m = n3; while (m) { int j = __ffs(m) - 1; m &= m - 1; racc += Wrs[(96 + j) * OO + ro]; }
            rp = LAM * rp + (1.0f - LAM) * racc;
            if (lane < OO) outb[(size_t)t * OO + lane] = rp;
        }
        p0 = n0; p1 = n1; p2 = n2; p3 = n3;
        gv = gn;
    }
}

// ---------------------------------------------------------------------------
// Launch
// ---------------------------------------------------------------------------
extern "C" void kernel_launch(void* const* d_in, const int* in_sizes, int n_in,
                              void* d_out, int out_size) {
    (void)in_sizes; (void)n_in; (void)out_size;
    const float* X  = (const float*)d_in[0];
    const float* W0 = (const float*)d_in[1];
    const float* W1 = (const float*)d_in[2];
    const float* V1 = (const float*)d_in[3];
    const float* Wr = (const float*)d_in[4];
    const float* br = (const float*)d_in[5];
    float* out = (float*)d_out;

    k_transpose_w0<<<(II * HH + 255) / 256, 256>>>(W0);
    k_masks<<<(NROWS + 7) / 8, 256>>>(X);

    const size_t smem_g = (size_t)CHUNK_I * 32 * sizeof(float4);  // 98,304 B
    cudaFuncSetAttribute(k_gather, cudaFuncAttributeMaxDynamicSharedMemorySize,
                         (int)smem_g);
    for (int c = 0; c < 4; c++)
        k_gather<<<296, 512, smem_g>>>(c);

    k_layer0<<<256, 256>>>();

    const size_t smem_g1 = (size_t)HH * HH * sizeof(float);       // 64 KB
    cudaFuncSetAttribute(k_gatherG, cudaFuncAttributeMaxDynamicSharedMemorySize,
                         (int)smem_g1);
    k_gatherG<<<296, 512, smem_g1>>>(W1);

    const size_t smem_l1 = (size_t)(HH * HH + HH * OO + 32) * sizeof(float)
                         + 16 * sizeof(unsigned);                 // ~76 KB
    cudaFuncSetAttribute(k_layer1, cudaFuncAttributeMaxDynamicSharedMemorySize,
                         (int)smem_l1);
    k_layer1<<<BB / 2, 256, smem_l1>>>(V1, Wr, br, out);
}

// round 8
// speedup vs baseline: 1.5791x; 1.3242x over previous
#include <cuda_runtime.h>

// Problem dims (fixed)
#define BB   512
#define TT   100
#define II   700
#define HH   128
#define OO   20
#define NROWS (BB*TT)
#define MW   24                    // padded mask words per row (22 used + 2 zero)
#define CHUNK_I 352                // i-rows per gather chunk (11 words)
#define CHUNK_W 11                 // mask words per chunk
#define TRANS_BLOCKS 350           // CTAs of fused kernel doing the transpose

#define ALPHA 0.81873075307798182f // exp(-0.2)
#define BETA  0.90483741803595957f // exp(-0.1)
#define LAM   0.95122942450071400f // exp(-0.05)

// Device-global scratch (allocation-free)
static __device__ float    g_W0T[II * HH];               // W0^T [i][h]
static __device__ unsigned g_masks[(size_t)NROWS * MW];  // input spike bitmasks (sequential)
static __device__ float    g_U[(size_t)NROWS * HH];      // U = X @ W0^T
static __device__ unsigned g_K0[(size_t)NROWS * 4];      // layer-0 spike masks
static __device__ float    g_G[(size_t)NROWS * HH];      // G = k0 @ W1^T

// ---------------------------------------------------------------------------
// K0 (launch 0): FUSED transpose + input-bitmask extraction.
// Blocks [0, TRANS_BLOCKS): W0 (H,I) -> W0^T (I,H).
// Remaining blocks: warp-per-row float4 spike masks, SEQUENTIAL bit order
// (word w bit j <-> element 32w+j — bit-exact with scalar encoding).
// ---------------------------------------------------------------------------
__global__ void __launch_bounds__(256) k_fused_tm(const float* __restrict__ W0,
                                                  const float* __restrict__ X) {
    if (blockIdx.x < TRANS_BLOCKS) {
        int idx = blockIdx.x * 256 + threadIdx.x;   // covers II*HH = 89600 exactly
        int i = idx >> 7, h = idx & 127;
        g_W0T[idx] = W0[h * II + i];
        return;
    }
    int warp = ((blockIdx.x - TRANS_BLOCKS) * 256 + threadIdx.x) >> 5;
    int lane = threadIdx.x & 31;
    if (warp >= NROWS) return;
    const float4* xr4 = (const float4*)(X + (size_t)warp * II);

    unsigned mw = 0;
    int myk = lane >> 2;
    int myg = lane & 3;
    #pragma unroll
    for (int k = 0; k < 6; k++) {
        float4 v = make_float4(0.f, 0.f, 0.f, 0.f);
        if (k < 5 || lane < 15)
            v = __ldg(xr4 + k * 32 + lane);
        unsigned nib = (v.x != 0.f ? 1u : 0u) | (v.y != 0.f ? 2u : 0u)
                     | (v.z != 0.f ? 4u : 0u) | (v.w != 0.f ? 8u : 0u);
        unsigned part = nib << ((lane & 7) * 4);
        part |= __shfl_xor_sync(0xffffffffu, part, 1);
        part |= __shfl_xor_sync(0xffffffffu, part, 2);
        part |= __shfl_xor_sync(0xffffffffu, part, 4);
        unsigned wd = __shfl_sync(0xffffffffu, part, myg * 8);
        if (k == myk) mw = wd;
    }
    if (lane < MW) g_masks[(size_t)warp * MW + lane] = mw;
}

// ---------------------------------------------------------------------------
// K1/K2 (launches 1,2): U chunk pass. Chunk c holds W0^T rows
// [352c, 352c+352) x 128 h in 176 KB SMEM (1 CTA/SM). Warp per row,
// float4 per lane. Running acc carried through g_U across the 2 launches;
// additions stay one-at-a-time ascending i -> bit-identical to one sweep.
// ---------------------------------------------------------------------------
__global__ void __launch_bounds__(512, 1) k_gather(int chunk) {
    extern __shared__ float4 Ws4[];            // [352][32] float4
    const int w0 = chunk * CHUNK_W;

    for (int idx = threadIdx.x; idx < CHUNK_I * 32; idx += 512) {
        int i = idx >> 5, q = idx & 31;
        int gi = chunk * CHUNK_I + i;
        float4 v = make_float4(0.f, 0.f, 0.f, 0.f);
        if (gi < II) v = *(const float4*)(g_W0T + gi * HH + q * 4);
        Ws4[idx] = v;
    }
    __syncthreads();

    int warp = threadIdx.x >> 5, lane = threadIdx.x & 31;
    for (int row = blockIdx.x * 16 + warp; row < NROWS; row += gridDim.x * 16) {
        unsigned mw = (lane < CHUNK_W)
                    ? g_masks[(size_t)row * MW + w0 + lane] : 0u;
        float4* up = (float4*)(g_U + (size_t)row * HH) + lane;
        float4 acc;
        if (chunk == 0) acc = make_float4(0.f, 0.f, 0.f, 0.f);
        else            acc = *up;
        #pragma unroll
        for (int w = 0; w < CHUNK_W; w++) {
            unsigned m = __shfl_sync(0xffffffffu, mw, w);
            int base = w * 32;
            while (m) {
                int j = __ffs(m) - 1;
                m &= m - 1;
                float4 v = Ws4[(base + j) * 32 + lane];
                acc.x += v.x; acc.y += v.y; acc.z += v.z; acc.w += v.w;
            }
        }
        *up = acc;
    }
}

// ---------------------------------------------------------------------------
// K3 (launch 3): layer-0 LIF scan, prefetch depth 4.
// ---------------------------------------------------------------------------
__global__ void __launch_bounds__(256) k_layer0() {
    int w = blockIdx.x * 8 + (threadIdx.x >> 5);
    int lane = threadIdx.x & 31;
    int b = w >> 2, c = w & 3;
    if (b >= BB) return;

    const float* Ub = g_U + (size_t)b * TT * HH + c * 32 + lane;
    unsigned* K0b = g_K0 + (size_t)b * TT * 4 + c;

    float s0 = 0.f, m0 = 0.f;
    float buf[4];
    #pragma unroll
    for (int r = 0; r < 4; r++) buf[r] = Ub[(size_t)r * HH];

    for (int t0 = 0; t0 < TT; t0 += 4) {
        float nxt[4];
        #pragma unroll
        for (int r = 0; r < 4; r++) {
            int tn = t0 + 4 + r;
            nxt[r] = (tn < TT) ? Ub[(size_t)tn * HH] : 0.f;
        }
        #pragma unroll
        for (int r = 0; r < 4; r++) {
            s0 = ALPHA * s0 + buf[r];
            m0 = BETA * m0 + s0;
            bool sp = m0 > 1.0f;
            if (sp) m0 = 0.f;
            unsigned bm = __ballot_sync(0xffffffffu, sp);
            if (lane == 0) K0b[(size_t)(t0 + r) * 4] = bm;
        }
        #pragma unroll
        for (int r = 0; r < 4; r++) buf[r] = nxt[r];
    }
}

// ---------------------------------------------------------------------------
// K4 (launch 4): G[row] = sum over active j (k0, ascending) of W1T[j].
// ---------------------------------------------------------------------------
__global__ void __launch_bounds__(512, 2) k_gatherG(const float* __restrict__ W1) {
    extern __shared__ float W1s[];             // [128][128]
    for (int idx = threadIdx.x; idx < HH * HH; idx += 512) {
        int h = idx >> 7, j = idx & 127;
        W1s[j * 128 + h] = W1[idx];
    }
    __syncthreads();

    int warp = threadIdx.x >> 5, lane = threadIdx.x & 31;
    for (int row = blockIdx.x * 16 + warp; row < NROWS; row += gridDim.x * 16) {
        unsigned mw = (lane < 4) ? g_K0[(size_t)row * 4 + lane] : 0u;
        float4 acc = make_float4(0.f, 0.f, 0.f, 0.f);
        #pragma unroll
        for (int q = 0; q < 4; q++) {
            unsigned m = __shfl_sync(0xffffffffu, mw, q);
            int base = q * 32;
            while (m) {
                int j = __ffs(m) - 1;
                m &= m - 1;
                float4 v = *(const float4*)(W1s + (base + j) * 128 + lane * 4);
                acc.x += v.x; acc.y += v.y; acc.z += v.z; acc.w += v.w;
            }
        }
        *(float4*)(g_G + (size_t)row * HH + lane * 4) = acc;
    }
}

// ---------------------------------------------------------------------------
// K5 (launch 5 — profiled): layer-1 recurrence, LEAN serial loop.
// 2 samples/CTA (256 thr), 2 CTAs/SM. Per-step: V-gather + LIF + ballot +
// barrier only. k1 masks go to SMEM history; readout + leaky scan run
// AFTER the loop (parallel tasks, identical arithmetic order -> bit-exact).
// ---------------------------------------------------------------------------
__global__ void __launch_bounds__(256, 2) k_layer1(
    const float* __restrict__ V1, const float* __restrict__ Wr,
    const float* __restrict__ br, float* __restrict__ out)
{
    extern __shared__ float sm6[];
    float* V1s = sm6;                               // 128*128      (64 KB)
    float* Wrs = V1s + HH * HH;                     // 128*20       (10 KB)
    float* brs = Wrs + HH * OO;                     // 32
    float* ybuf = brs + 32;                         // 2*100*20     (16 KB)
    unsigned* hist = (unsigned*)(ybuf + 2 * TT * OO); // 2*100*4    (3.2 KB)

    for (int idx = threadIdx.x; idx < HH * HH; idx += 256) {
        int h = idx >> 7, j = idx & 127;
        V1s[j * 128 + h] = V1[idx];
    }
    for (int idx = threadIdx.x; idx < OO * HH; idx += 256) {
        int o = idx >> 7, j = idx & 127;
        Wrs[j * OO + o] = Wr[idx];
    }
    if (threadIdx.x < OO) brs[threadIdx.x] = br[threadIdx.x];
    __syncthreads();

    int g    = threadIdx.x >> 7;     // sample in CTA
    int h    = threadIdx.x & 127;    // neuron
    int word = h >> 5;
    int lane = threadIdx.x & 31;
    int b    = blockIdx.x * 2 + g;
    unsigned* hg = hist + g * TT * 4;
    float* yg = ybuf + g * TT * OO;
    int barid = g + 1;

    const float* Gb = g_G + (size_t)b * TT * HH;
    float* outb = out + (size_t)b * TT * OO;

    float s1 = 0.f, m1 = 0.f;
    unsigned p0 = 0, p1 = 0, p2 = 0, p3 = 0;
    float gv = Gb[h];
    float g1 = Gb[HH + h];

    for (int t = 0; t < TT; t++) {
        float g2 = (t + 2 < TT) ? Gb[(size_t)(t + 2) * HH + h] : 0.f;

        float acc = 0.f;
        unsigned m;
        m = p0; while (m) { int j = __ffs(m) - 1; m &= m - 1; acc += V1s[j * 128 + h]; }
        m = p1; while (m) { int j = __ffs(m) - 1; m &= m - 1; acc += V1s[(32 + j) * 128 + h]; }
        m = p2; while (m) { int j = __ffs(m) - 1; m &= m - 1; acc += V1s[(64 + j) * 128 + h]; }
        m = p3; while (m) { int j = __ffs(m) - 1; m &= m - 1; acc += V1s[(96 + j) * 128 + h]; }

        s1 = (ALPHA * s1 + gv) + acc;
        m1 = BETA * m1 + s1;
        bool sp = m1 > 1.0f;
        if (sp) m1 = 0.f;

        unsigned bm = __ballot_sync(0xffffffffu, sp);
        if (lane == 0) hg[t * 4 + word] = bm;
        asm volatile("bar.sync %0, %1;" :: "r"(barid), "r"(128) : "memory");
        p0 = hg[t * 4 + 0]; p1 = hg[t * 4 + 1];
        p2 = hg[t * 4 + 2]; p3 = hg[t * 4 + 3];
        gv = g1; g1 = g2;
    }

    // Post-loop readout: 2000 (t,o) tasks over the group's 128 threads.
    // Per task: racc = br[o] + sum over active j (ascending) of Wr[o][j]
    // -> identical order to the fused version.
    for (int task = h; task < TT * OO; task += HH) {
        int t = task / OO, o = task - t * OO;
        float racc = brs[o];
        #pragma unroll
        for (int q = 0; q < 4; q++) {
            unsigned m = hg[t * 4 + q];
            int base = q * 32;
            while (m) {
                int j = __ffs(m) - 1;
                m &= m - 1;
                racc += Wrs[(base + j) * OO + o];
            }
        }
        yg[t * OO + o] = racc;
    }
    asm volatile("bar.sync %0, %1;" :: "r"(barid), "r"(128) : "memory");

    // Leaky scan per output channel (threads h < 20), identical rp chain.
    if (h < OO) {
        const float C = 1.0f - LAM;
        float rp = 0.f;
        for (int t = 0; t < TT; t++) {
            rp = LAM * rp + C * yg[t * OO + h];
            outb[(size_t)t * OO + h] = rp;
        }
    }
}

// ---------------------------------------------------------------------------
// Launch
// ---------------------------------------------------------------------------
extern "C" void kernel_launch(void* const* d_in, const int* in_sizes, int n_in,
                              void* d_out, int out_size) {
    (void)in_sizes; (void)n_in; (void)out_size;
    const float* X  = (const float*)d_in[0];
    const float* W0 = (const float*)d_in[1];
    const float* W1 = (const float*)d_in[2];
    const float* V1 = (const float*)d_in[3];
    const float* Wr = (const float*)d_in[4];
    const float* br = (const float*)d_in[5];
    float* out = (float*)d_out;

    k_fused_tm<<<TRANS_BLOCKS + (NROWS + 7) / 8, 256>>>(W0, X);

    const size_t smem_g = (size_t)CHUNK_I * 32 * sizeof(float4);  // 180,224 B
    cudaFuncSetAttribute(k_gather, cudaFuncAttributeMaxDynamicSharedMemorySize,
                         (int)smem_g);
    k_gather<<<148, 512, smem_g>>>(0);
    k_gather<<<148, 512, smem_g>>>(1);

    k_layer0<<<256, 256>>>();

    const size_t smem_g1 = (size_t)HH * HH * sizeof(float);       // 64 KB
    cudaFuncSetAttribute(k_gatherG, cudaFuncAttributeMaxDynamicSharedMemorySize,
                         (int)smem_g1);
    k_gatherG<<<296, 512, smem_g1>>>(W1);

    const size_t smem_l1 = (size_t)(HH * HH + HH * OO + 32 + 2 * TT * OO) * sizeof(float)
                         + 2 * TT * 4 * sizeof(unsigned);         // ~93.5 KB
    cudaFuncSetAttribute(k_layer1, cudaFuncAttributeMaxDynamicSharedMemorySize,
                         (int)smem_l1);
    k_layer1<<<BB / 2, 256, smem_l1>>>(V1, Wr, br, out);
}